// round 8
// baseline (speedup 1.0000x reference)
#include <cuda_runtime.h>
#include <cuda_bf16.h>

// Problem constants (fixed by the reference's setup)
#define SIZE   129
#define BZ2    64
#define BZX    65
#define MARGIN 3
#define GZ     135          // SIZE + 2*MARGIN
#define GY     135
#define GX     68           // BZX + MARGIN
#define NPTS   (SIZE * BZX) // 8385
#define NBATCH 256
#define NIN    8

// 4 lanes cooperate per output point; lane q handles the 16B quarter of the
// 64B weight row. Corner loop is branch-free straight-line code so ptxas can
// software-pipeline the gathers (reg-capped for occupancy). Bias accumulation
// is distributed across the quad (lane q handles corners q and q+4) instead
// of serializing 8 loads on lane 0.
__global__ __launch_bounds__(256, 6) void trilinear_proj_kernel(
    const float* __restrict__ input,    // [256, 8]
    const float* __restrict__ weight,   // [W, 8, 2]
    const float* __restrict__ bias,     // [W, 2]
    const int*   __restrict__ gidx,     // [135, 135, 68]
    const float* __restrict__ rot,      // [256, 3, 3]
    float*       __restrict__ out)      // [256, NPTS, 2]
{
    __shared__ float sIn[NIN];
    __shared__ float sR[9];

    const int b   = blockIdx.y;
    const int tid = threadIdx.x;
    if (tid < NIN) sIn[tid] = input[b * NIN + tid];
    if (tid < 9)   sR[tid]  = rot[b * 9 + tid];
    __syncthreads();

    const int t = blockIdx.x * 256 + tid;
    const int n = t >> 2;          // point index
    const int q = t & 3;           // quarter within the weight row
    if (n >= NPTS) return;         // quad-granular -> quads stay intact

    // shfl mask covering exactly this quad
    const unsigned qmask = 0xFu << ((tid & 31) & ~3);

    // This lane's two input features
    const float iA = sIn[2 * q];
    const float iB = sIn[2 * q + 1];

    const float r00 = sR[0], r01 = sR[1];
    const float r10 = sR[3], r11 = sR[4];
    const float r20 = sR[6], r21 = sR[7];

    // grid2d coords derived arithmetically: n = iy*BZX + ix, y = iy-BZ2, x = ix
    const float y2 = (float)(n / BZX - BZ2);
    const float x2 = (float)(n % BZX);

    // c = R @ (x2, y2, 0), fp32, no fma contraction (bit-critical at the
    // r^2 = 4096 boundary lattice points, where one product is exactly zero).
    float cx = __fadd_rn(__fmul_rn(r00, x2), __fmul_rn(r01, y2));
    float cy = __fadd_rn(__fmul_rn(r10, x2), __fmul_rn(r11, y2));
    float cz = __fadd_rn(__fmul_rn(r20, x2), __fmul_rn(r21, y2));

    float sign = 1.0f;
    if (cx < 0.0f) { cx = -cx; cy = -cy; cz = -cz; sign = -1.0f; }

    // inside = sum(c*c) < 64^2 with the reference's Triton half-split tree:
    // q = (s1 + s3) + s2, rounded elementwise squares, no fma contraction.
    const float s1 = __fmul_rn(cx, cx);
    const float s2 = __fmul_rn(cy, cy);
    const float s3 = __fmul_rn(cz, cz);
    const float r2 = __fadd_rn(__fadd_rn(s1, s3), s2);
    const bool inside = (r2 < 4096.0f);

    float accR = 0.0f, accI = 0.0f;

    if (inside) {
        const float fxf = floorf(cx), fyf = floorf(cy), fzf = floorf(cz);
        const float fx = cx - fxf, fy = cy - fyf, fz = cz - fzf;
        const int   bx = (int)fxf, by = (int)fyf, bz = (int)fzf;

        const int ix0 = min(max(bx,              0), GX - 1);
        const int ix1 = min(max(bx + 1,          0), GX - 1);
        const int iy0 = min(max(by + BZ2 + MARGIN,     0), GY - 1);
        const int iy1 = min(max(by + 1 + BZ2 + MARGIN, 0), GY - 1);
        const int iz0 = min(max(bz + BZ2 + MARGIN,     0), GZ - 1);
        const int iz1 = min(max(bz + 1 + BZ2 + MARGIN, 0), GZ - 1);

        const int zs0 = iz0 * (GY * GX), zs1 = iz1 * (GY * GX);
        const int ys0 = iy0 * GX,        ys1 = iy1 * GX;

        // All 8 index gathers up front (quad lanes hit identical addresses ->
        // broadcast within the L1tex wavefront)
        int idx[8];
        idx[0] = gidx[zs0 + ys0 + ix0];
        idx[1] = gidx[zs0 + ys0 + ix1];
        idx[2] = gidx[zs0 + ys1 + ix0];
        idx[3] = gidx[zs0 + ys1 + ix1];
        idx[4] = gidx[zs1 + ys0 + ix0];
        idx[5] = gidx[zs1 + ys0 + ix1];
        idx[6] = gidx[zs1 + ys1 + ix0];
        idx[7] = gidx[zs1 + ys1 + ix1];

        const float wx0 = 1.0f - fx, wx1 = fx;
        const float wy0 = 1.0f - fy, wy1 = fy;
        const float wz0 = 1.0f - fz, wz1 = fz;
        float cw[8];
        cw[0] = wz0 * wy0 * wx0;
        cw[1] = wz0 * wy0 * wx1;
        cw[2] = wz0 * wy1 * wx0;
        cw[3] = wz0 * wy1 * wx1;
        cw[4] = wz1 * wy0 * wx0;
        cw[5] = wz1 * wy0 * wx1;
        cw[6] = wz1 * wy1 * wx0;
        cw[7] = wz1 * wy1 * wx1;

        // Bias: lane q handles corners q and q+4 (SEL chains, not dynamic
        // register-array indexing). Loads issue early, overlap with weights.
        const int idb0 = (q == 0) ? idx[0] : (q == 1) ? idx[1] : (q == 2) ? idx[2] : idx[3];
        const int idb1 = (q == 0) ? idx[4] : (q == 1) ? idx[5] : (q == 2) ? idx[6] : idx[7];
        const float cwb0 = (q == 0) ? cw[0] : (q == 1) ? cw[1] : (q == 2) ? cw[2] : cw[3];
        const float cwb1 = (q == 0) ? cw[4] : (q == 1) ? cw[5] : (q == 2) ? cw[6] : cw[7];
        const float2 bb0 = reinterpret_cast<const float2*>(bias)[max(idb0, 0)];
        const float2 bb1 = reinterpret_cast<const float2*>(bias)[max(idb1, 0)];
        const float wb0 = (idb0 >= 0) ? cwb0 : 0.0f;
        const float wb1 = (idb1 >= 0) ? cwb1 : 0.0f;

        const float* wbase = weight + q * 4;

        // Branch-free straight-line corner loop: clamped-index load, masked
        // accumulate. ptxas software-pipelines the loads up to the reg cap.
        #pragma unroll
        for (int k = 0; k < 8; k++) {
            const int id   = idx[k];
            const int safe = max(id, 0);
            const float4 wq = *reinterpret_cast<const float4*>(
                wbase + (size_t)safe * 16);
            const float w = (id >= 0) ? cw[k] : 0.0f;
            accR += w * (iA * wq.x + iB * wq.z);
            accI += w * (iA * wq.y + iB * wq.w);
        }

        accR += wb0 * bb0.x + wb1 * bb1.x;
        accI += wb0 * bb0.y + wb1 * bb1.y;
    }

    // Combine the 4 partial dots of the quad
    accR += __shfl_xor_sync(qmask, accR, 1);
    accI += __shfl_xor_sync(qmask, accI, 1);
    accR += __shfl_xor_sync(qmask, accR, 2);
    accI += __shfl_xor_sync(qmask, accI, 2);

    if (q == 0) {
        float2* o = reinterpret_cast<float2*>(out) + (size_t)b * NPTS + n;
        *o = make_float2(accR, sign * accI);
    }
}

extern "C" void kernel_launch(void* const* d_in, const int* in_sizes, int n_in,
                              void* d_out, int out_size) {
    const float* input  = (const float*)d_in[0];
    const float* weight = (const float*)d_in[1];
    const float* bias   = (const float*)d_in[2];
    const int*   gidx   = (const int*)  d_in[3];
    const float* rot    = (const float*)d_in[4];
    // d_in[5] = grid2d_coord (derived arithmetically), d_in[6] = max_r (hardcoded)

    float* out = (float*)d_out;

    dim3 block(256);
    dim3 grid((NPTS * 4 + 255) / 256, NBATCH);   // 4 lanes per point
    trilinear_proj_kernel<<<grid, block>>>(input, weight, bias, gidx, rot, out);
}

// round 9
// speedup vs baseline: 1.5082x; 1.5082x over previous
#include <cuda_runtime.h>
#include <cuda_bf16.h>

// Problem constants (fixed by the reference's setup)
#define SIZE   129
#define BZ2    64
#define BZX    65
#define MARGIN 3
#define GZ     135          // SIZE + 2*MARGIN
#define GY     135
#define GX     68           // BZX + MARGIN
#define GYGX   (GY * GX)
#define NPTS   (SIZE * BZX) // 8385
#define NBATCH 256
#define NIN    8

// 4 lanes cooperate per output point; lane q handles the 16B quarter of the
// 64B weight row. For inside points the reference's jnp.clip never binds
// (cx in [0,64), |cy|,|cz| < 64), so corner addresses are base + constant
// immediates -- no clamp ALU, short address chain before the idx gathers.
__global__ __launch_bounds__(256, 8) void trilinear_proj_kernel(
    const float* __restrict__ input,    // [256, 8]
    const float* __restrict__ weight,   // [W, 8, 2]
    const float* __restrict__ bias,     // [W, 2]
    const int*   __restrict__ gidx,     // [135, 135, 68]
    const float* __restrict__ rot,      // [256, 3, 3]
    float*       __restrict__ out)      // [256, NPTS, 2]
{
    __shared__ float sIn[NIN];
    __shared__ float sR[9];

    const int b   = blockIdx.y;
    const int tid = threadIdx.x;
    if (tid < NIN) sIn[tid] = input[b * NIN + tid];
    if (tid < 9)   sR[tid]  = rot[b * 9 + tid];
    __syncthreads();

    const int t = blockIdx.x * 256 + tid;
    const int n = t >> 2;          // point index
    const int q = t & 3;           // quarter within the weight row
    if (n >= NPTS) return;         // quad-granular -> quads stay intact

    // shfl mask covering exactly this quad
    const unsigned qmask = 0xFu << ((tid & 31) & ~3);

    // This lane's two input features
    const float iA = sIn[2 * q];
    const float iB = sIn[2 * q + 1];

    const float r00 = sR[0], r01 = sR[1];
    const float r10 = sR[3], r11 = sR[4];
    const float r20 = sR[6], r21 = sR[7];

    // grid2d coords derived arithmetically: n = iy*BZX + ix, y = iy-BZ2, x = ix
    const float y2 = (float)(n / BZX - BZ2);
    const float x2 = (float)(n % BZX);

    // c = R @ (x2, y2, 0), fp32, no fma contraction (bit-critical at the
    // r^2 = 4096 boundary lattice points, where one product is exactly zero).
    float cx = __fadd_rn(__fmul_rn(r00, x2), __fmul_rn(r01, y2));
    float cy = __fadd_rn(__fmul_rn(r10, x2), __fmul_rn(r11, y2));
    float cz = __fadd_rn(__fmul_rn(r20, x2), __fmul_rn(r21, y2));

    float sign = 1.0f;
    if (cx < 0.0f) { cx = -cx; cy = -cy; cz = -cz; sign = -1.0f; }

    // inside = sum(c*c) < 64^2 with the reference's Triton half-split tree:
    // q = (s1 + s3) + s2, rounded elementwise squares, no fma contraction.
    const float s1 = __fmul_rn(cx, cx);
    const float s2 = __fmul_rn(cy, cy);
    const float s3 = __fmul_rn(cz, cz);
    const float r2 = __fadd_rn(__fadd_rn(s1, s3), s2);
    const bool inside = (r2 < 4096.0f);

    float accR = 0.0f, accI = 0.0f;

    if (inside) {
        const float fxf = floorf(cx), fyf = floorf(cy), fzf = floorf(cz);
        const float fx = cx - fxf, fy = cy - fyf, fz = cz - fzf;

        // For inside points: bx in [0,63], by,bz in [-64,63] -> none of the
        // reference's clips bind. Single base address + constant offsets.
        const int bx = (int)fxf;
        const int by = (int)fyf;
        const int bz = (int)fzf;
        const int base = (bz + BZ2 + MARGIN) * GYGX
                       + (by + BZ2 + MARGIN) * GX
                       + bx;

        // All 8 index gathers up front (quad lanes hit identical addresses ->
        // broadcast within the L1tex wavefront)
        int idx[8];
        idx[0] = gidx[base];
        idx[1] = gidx[base + 1];
        idx[2] = gidx[base + GX];
        idx[3] = gidx[base + GX + 1];
        idx[4] = gidx[base + GYGX];
        idx[5] = gidx[base + GYGX + 1];
        idx[6] = gidx[base + GYGX + GX];
        idx[7] = gidx[base + GYGX + GX + 1];

        const float wx0 = 1.0f - fx, wx1 = fx;
        const float wy0 = 1.0f - fy, wy1 = fy;
        const float wz0 = 1.0f - fz, wz1 = fz;
        float cw[8];
        cw[0] = wz0 * wy0 * wx0;
        cw[1] = wz0 * wy0 * wx1;
        cw[2] = wz0 * wy1 * wx0;
        cw[3] = wz0 * wy1 * wx1;
        cw[4] = wz1 * wy0 * wx0;
        cw[5] = wz1 * wy0 * wx1;
        cw[6] = wz1 * wy1 * wx0;
        cw[7] = wz1 * wy1 * wx1;

        const float* wbase = weight + q * 4;
        const bool lane0 = (q == 0);

        // Branch-free straight-line corner loop: clamped-index load, masked
        // accumulate. ptxas software-pipelines the loads up to the reg cap.
        #pragma unroll
        for (int k = 0; k < 8; k++) {
            const int id   = idx[k];
            const int safe = max(id, 0);
            const float4 wq = *reinterpret_cast<const float4*>(
                wbase + (size_t)safe * 16);
            const float w = (id >= 0) ? cw[k] : 0.0f;
            float vr = iA * wq.x + iB * wq.z;
            float vi = iA * wq.y + iB * wq.w;
            if (lane0) {
                const float2 bb = reinterpret_cast<const float2*>(bias)[safe];
                vr += bb.x;
                vi += bb.y;
            }
            accR += w * vr;
            accI += w * vi;
        }
    }

    // Combine the 4 partial dots of the quad
    accR += __shfl_xor_sync(qmask, accR, 1);
    accI += __shfl_xor_sync(qmask, accI, 1);
    accR += __shfl_xor_sync(qmask, accR, 2);
    accI += __shfl_xor_sync(qmask, accI, 2);

    if (q == 0) {
        float2* o = reinterpret_cast<float2*>(out) + (size_t)b * NPTS + n;
        *o = make_float2(accR, sign * accI);
    }
}

extern "C" void kernel_launch(void* const* d_in, const int* in_sizes, int n_in,
                              void* d_out, int out_size) {
    const float* input  = (const float*)d_in[0];
    const float* weight = (const float*)d_in[1];
    const float* bias   = (const float*)d_in[2];
    const int*   gidx   = (const int*)  d_in[3];
    const float* rot    = (const float*)d_in[4];
    // d_in[5] = grid2d_coord (derived arithmetically), d_in[6] = max_r (hardcoded)

    float* out = (float*)d_out;

    dim3 block(256);
    dim3 grid((NPTS * 4 + 255) / 256, NBATCH);   // 4 lanes per point
    trilinear_proj_kernel<<<grid, block>>>(input, weight, bias, gidx, rot, out);
}